// round 1
// baseline (speedup 1.0000x reference)
#include <cuda_runtime.h>

// Shapes (fixed by the problem): inputs [L,B,C,H,W] fp32, W [C,C] fp32
#define DL 4
#define DB 8
#define DC 256
#define DHW 4096            // 64*64
#define LBC (DL*DB*DC)      // 8192
#define VEC_PER_LBC 1024    // 4096/4 float4 per (l,b,c) row

__device__ float g_gap[LBC];
__device__ float g_attn[LBC];

// ---------------------------------------------------------------------------
// Kernel 1: global average pool. One block per (l,b,c); 256 threads reduce the
// contiguous 4096-float spatial slab via float4 loads + shuffle reduction.
// ---------------------------------------------------------------------------
__global__ void __launch_bounds__(256) gap_kernel(const float* __restrict__ in) {
    const int lbc = blockIdx.x;
    const float4* p = reinterpret_cast<const float4*>(in) + (size_t)lbc * VEC_PER_LBC;
    const int t = threadIdx.x;

    float s = 0.0f;
#pragma unroll
    for (int i = 0; i < 4; ++i) {
        float4 v = p[i * 256 + t];           // fully coalesced
        s += (v.x + v.y) + (v.z + v.w);
    }
    // warp reduce
#pragma unroll
    for (int o = 16; o > 0; o >>= 1) s += __shfl_xor_sync(0xffffffffu, s, o);

    __shared__ float ws[8];
    if ((t & 31) == 0) ws[t >> 5] = s;
    __syncthreads();
    if (t < 8) {
        float v = ws[t];
#pragma unroll
        for (int o = 4; o > 0; o >>= 1) v += __shfl_xor_sync(0xffu, v, o);
        if (t == 0) g_gap[lbc] = v * (1.0f / (float)DHW);
    }
}

// ---------------------------------------------------------------------------
// Kernel 2: scores = gap @ W^T, softmax over L per (b, d). 8 blocks (one per
// batch) x 256 threads (one per output channel d). Tiny; W stays in L2.
// ---------------------------------------------------------------------------
__global__ void __launch_bounds__(256) attn_kernel(const float* __restrict__ Wm) {
    const int b = blockIdx.x;
    const int d = threadIdx.x;

    __shared__ float gs[DL][DC];
#pragma unroll
    for (int l = 0; l < DL; ++l) gs[l][d] = g_gap[(l * DB + b) * DC + d];
    __syncthreads();

    float sc[DL] = {0.f, 0.f, 0.f, 0.f};
    const float* wr = Wm + d * DC;           // row d of W ([out,in])
#pragma unroll 4
    for (int c = 0; c < DC; ++c) {
        const float w = wr[c];
#pragma unroll
        for (int l = 0; l < DL; ++l) sc[l] = fmaf(gs[l][c], w, sc[l]);
    }

    float m = sc[0];
#pragma unroll
    for (int l = 1; l < DL; ++l) m = fmaxf(m, sc[l]);
    float e[DL], sum = 0.f;
#pragma unroll
    for (int l = 0; l < DL; ++l) { e[l] = __expf(sc[l] - m); sum += e[l]; }
    const float inv = 1.0f / sum;
#pragma unroll
    for (int l = 0; l < DL; ++l) g_attn[(l * DB + b) * DC + d] = e[l] * inv;
}

// ---------------------------------------------------------------------------
// Kernel 3: out = in * attn[l,b,c] (broadcast over 4096 spatial elems).
// Flat float4 streaming; attn index = vec_idx >> 10.
// ---------------------------------------------------------------------------
__global__ void __launch_bounds__(256) mul_kernel(const float* __restrict__ in,
                                                  float* __restrict__ out) {
    const int idx = blockIdx.x * 256 + threadIdx.x;   // float4 index
    const int lbc = idx >> 10;
    const float a = __ldg(&g_attn[lbc]);
    float4 v = reinterpret_cast<const float4*>(in)[idx];
    v.x *= a; v.y *= a; v.z *= a; v.w *= a;
    reinterpret_cast<float4*>(out)[idx] = v;
}

// ---------------------------------------------------------------------------
extern "C" void kernel_launch(void* const* d_in, const int* in_sizes, int n_in,
                              void* d_out, int out_size) {
    const float* in = (const float*)d_in[0];   // [L,B,C,H,W]
    const float* Wm = (const float*)d_in[1];   // [C,C]
    float* out = (float*)d_out;

    gap_kernel<<<LBC, 256>>>(in);
    attn_kernel<<<DB, 256>>>(Wm);
    const int total_vec = LBC * VEC_PER_LBC;   // 8,388,608
    mul_kernel<<<total_vec / 256, 256>>>(in, out);
}

// round 2
// speedup vs baseline: 1.1055x; 1.1055x over previous
#include <cuda_runtime.h>

// Shapes (fixed by the problem): inputs [L,B,C,H,W] fp32, W [C,C] fp32
#define DL 4
#define DB 8
#define DC 256
#define DHW 4096            // 64*64
#define LBC (DL*DB*DC)      // 8192
#define VEC_PER_LBC 1024    // 4096/4 float4 per (l,b,c) row

__device__ float g_gap[LBC];
__device__ float g_attn[LBC];

// ---------------------------------------------------------------------------
// Kernel 1: global average pool. One block per (l,b,c); 256 threads reduce the
// contiguous 4096-float spatial slab via float4 loads + shuffle reduction.
// Default cache policy on purpose: these reads populate L2 for the mul pass.
// ---------------------------------------------------------------------------
__global__ void __launch_bounds__(256) gap_kernel(const float* __restrict__ in) {
    const int lbc = blockIdx.x;
    const float4* p = reinterpret_cast<const float4*>(in) + (size_t)lbc * VEC_PER_LBC;
    const int t = threadIdx.x;

    float4 v[4];
#pragma unroll
    for (int i = 0; i < 4; ++i) v[i] = p[i * 256 + t];   // front-batched, coalesced

    float s = 0.0f;
#pragma unroll
    for (int i = 0; i < 4; ++i) s += (v[i].x + v[i].y) + (v[i].z + v[i].w);

    // warp reduce
#pragma unroll
    for (int o = 16; o > 0; o >>= 1) s += __shfl_xor_sync(0xffffffffu, s, o);

    __shared__ float ws[8];
    if ((t & 31) == 0) ws[t >> 5] = s;
    __syncthreads();
    if (t < 8) {
        float r = ws[t];
#pragma unroll
        for (int o = 4; o > 0; o >>= 1) r += __shfl_xor_sync(0xffu, r, o);
        if (t == 0) g_gap[lbc] = r * (1.0f / (float)DHW);
    }
}

// ---------------------------------------------------------------------------
// Kernel 2: scores = gap @ W^T, softmax over L per (b, d). 8 blocks (one per
// batch) x 256 threads (one per output channel d). Tiny; W stays in L2.
// ---------------------------------------------------------------------------
__global__ void __launch_bounds__(256) attn_kernel(const float* __restrict__ Wm) {
    const int b = blockIdx.x;
    const int d = threadIdx.x;

    __shared__ float gs[DL][DC];
#pragma unroll
    for (int l = 0; l < DL; ++l) gs[l][d] = g_gap[(l * DB + b) * DC + d];
    __syncthreads();

    float sc[DL] = {0.f, 0.f, 0.f, 0.f};
    const float* wr = Wm + d * DC;           // row d of W ([out,in])
#pragma unroll 4
    for (int c = 0; c < DC; ++c) {
        const float w = wr[c];
#pragma unroll
        for (int l = 0; l < DL; ++l) sc[l] = fmaf(gs[l][c], w, sc[l]);
    }

    float m = sc[0];
#pragma unroll
    for (int l = 1; l < DL; ++l) m = fmaxf(m, sc[l]);
    float e[DL], sum = 0.f;
#pragma unroll
    for (int l = 0; l < DL; ++l) { e[l] = __expf(sc[l] - m); sum += e[l]; }
    const float inv = 1.0f / sum;
#pragma unroll
    for (int l = 0; l < DL; ++l) g_attn[(l * DB + b) * DC + d] = e[l] * inv;
}

// ---------------------------------------------------------------------------
// Kernel 3: out = in * attn[l,b,c]. One block per (l,b,c), processed in
// REVERSE block order so the tail of the input (still resident in L2 from the
// gap pass) is re-read as L2 hits. Reads are evict-first (__ldcs, no reuse
// after this) and stores are evict-first (__stcs) so output lines don't
// displace the remaining input window.
// ---------------------------------------------------------------------------
__global__ void __launch_bounds__(256) mul_kernel(const float* __restrict__ in,
                                                  float* __restrict__ out) {
    const int rb = (int)gridDim.x - 1 - (int)blockIdx.x;   // reverse traversal
    const size_t base = (size_t)rb * VEC_PER_LBC;
    const int t = threadIdx.x;

    const float a = g_attn[rb];                            // one (l,b,c) per block
    const float4* p = reinterpret_cast<const float4*>(in) + base;
    float4* q = reinterpret_cast<float4*>(out) + base;

    float4 v[4];
#pragma unroll
    for (int i = 0; i < 4; ++i) v[i] = __ldcs(&p[i * 256 + t]);  // MLP=4
#pragma unroll
    for (int i = 0; i < 4; ++i) {
        v[i].x *= a; v[i].y *= a; v[i].z *= a; v[i].w *= a;
        __stcs(&q[i * 256 + t], v[i]);
    }
}

// ---------------------------------------------------------------------------
extern "C" void kernel_launch(void* const* d_in, const int* in_sizes, int n_in,
                              void* d_out, int out_size) {
    const float* in = (const float*)d_in[0];   // [L,B,C,H,W]
    const float* Wm = (const float*)d_in[1];   // [C,C]
    float* out = (float*)d_out;

    gap_kernel<<<LBC, 256>>>(in);
    attn_kernel<<<DB, 256>>>(Wm);
    mul_kernel<<<LBC, 256>>>(in, out);
}

// round 3
// speedup vs baseline: 1.7504x; 1.5833x over previous
#include <cuda_runtime.h>

// Shapes (fixed by the problem): inputs [L,B,C,H,W] fp32, W [C,C] fp32
#define DL 4
#define DB 8
#define DC 256
#define DHW 4096            // 64*64
#define LBC (DL*DB*DC)      // 8192
#define VEC_PER_LBC 1024    // 4096/4 float4 per (l,b,c) row

__device__ float g_gap[LBC];

// ---------------------------------------------------------------------------
// Kernel 1: global average pool. One block per TWO (l,b,c) rows; 256 threads,
// 8 front-batched float4 loads per thread (MLP_p1=8), dual shuffle reduction.
// Default cache policy: these fills populate L2 for the fused pass.
// ---------------------------------------------------------------------------
__global__ void __launch_bounds__(256) gap_kernel(const float* __restrict__ in) {
    const int pair = blockIdx.x;                       // 0..4095
    const float4* p = reinterpret_cast<const float4*>(in) + (size_t)pair * (2 * VEC_PER_LBC);
    const int t = threadIdx.x;

    float4 v[8];
#pragma unroll
    for (int i = 0; i < 8; ++i) v[i] = p[i * 256 + t]; // front-batched, coalesced

    float s0 = 0.f, s1 = 0.f;
#pragma unroll
    for (int i = 0; i < 4; ++i) s0 += (v[i].x + v[i].y) + (v[i].z + v[i].w);
#pragma unroll
    for (int i = 4; i < 8; ++i) s1 += (v[i].x + v[i].y) + (v[i].z + v[i].w);

#pragma unroll
    for (int o = 16; o > 0; o >>= 1) {
        s0 += __shfl_xor_sync(0xffffffffu, s0, o);
        s1 += __shfl_xor_sync(0xffffffffu, s1, o);
    }

    __shared__ float ws[8][2];
    if ((t & 31) == 0) { ws[t >> 5][0] = s0; ws[t >> 5][1] = s1; }
    __syncthreads();
    if (t == 0) {
        float a = 0.f, b = 0.f;
#pragma unroll
        for (int w = 0; w < 8; ++w) { a += ws[w][0]; b += ws[w][1]; }
        g_gap[2 * pair + 0] = a * (1.0f / (float)DHW);
        g_gap[2 * pair + 1] = b * (1.0f / (float)DHW);
    }
}

// ---------------------------------------------------------------------------
// Kernel 2 (fused): per-block attention compute + broadcast multiply.
// One block per (l,b,c)=rb, reverse traversal. Front-batch the 4 input float4
// loads, then while they're in flight compute the 4 scores for (b, d=c):
//   sc[l] = sum_c gap[l,b,c] * W[d,c]   (block-wide reduction)
// softmax over l, pick this block's l, multiply, stream out with __stcs.
// ---------------------------------------------------------------------------
__global__ void __launch_bounds__(256) fused_mul_kernel(const float* __restrict__ in,
                                                         const float* __restrict__ Wm,
                                                         float* __restrict__ out) {
    const int rb = (int)gridDim.x - 1 - (int)blockIdx.x;   // reverse traversal
    const int l0 = rb >> 11;            // rb / (DB*DC)
    const int b  = (rb >> 8) & (DB - 1);
    const int d  = rb & (DC - 1);
    const int t  = threadIdx.x;

    const size_t base = (size_t)rb * VEC_PER_LBC;
    const float4* p = reinterpret_cast<const float4*>(in) + base;
    float4* q = reinterpret_cast<float4*>(out) + base;

    // 1) front-batch the big DRAM loads (MLP=4) — attn math hides under them
    float4 v[4];
#pragma unroll
    for (int i = 0; i < 4; ++i) v[i] = p[i * 256 + t];

    // 2) attention scores: thread t owns input-channel c=t
    const float wv = __ldg(&Wm[d * DC + t]);
    float part[DL];
#pragma unroll
    for (int l = 0; l < DL; ++l) part[l] = wv * g_gap[(l * DB + b) * DC + t];

#pragma unroll
    for (int o = 16; o > 0; o >>= 1)
#pragma unroll
        for (int l = 0; l < DL; ++l) part[l] += __shfl_xor_sync(0xffffffffu, part[l], o);

    __shared__ float sred[8][DL];
    if ((t & 31) == 0) {
#pragma unroll
        for (int l = 0; l < DL; ++l) sred[t >> 5][l] = part[l];
    }
    __syncthreads();

    float sc[DL];
#pragma unroll
    for (int l = 0; l < DL; ++l) {
        float s = 0.f;
#pragma unroll
        for (int w = 0; w < 8; ++w) s += sred[w][l];   // smem broadcast, conflict-free
        sc[l] = s;
    }

    // 3) softmax over L, select this block's level
    float m = sc[0];
#pragma unroll
    for (int l = 1; l < DL; ++l) m = fmaxf(m, sc[l]);
    float sum = 0.f, el0 = 0.f;
#pragma unroll
    for (int l = 0; l < DL; ++l) {
        float e = __expf(sc[l] - m);
        sum += e;
        if (l == l0) el0 = e;
    }
    const float a = el0 / sum;

    // 4) multiply + stream out (evict-first stores)
#pragma unroll
    for (int i = 0; i < 4; ++i) {
        v[i].x *= a; v[i].y *= a; v[i].z *= a; v[i].w *= a;
        __stcs(&q[i * 256 + t], v[i]);
    }
}

// ---------------------------------------------------------------------------
extern "C" void kernel_launch(void* const* d_in, const int* in_sizes, int n_in,
                              void* d_out, int out_size) {
    const float* in = (const float*)d_in[0];   // [L,B,C,H,W]
    const float* Wm = (const float*)d_in[1];   // [C,C]
    float* out = (float*)d_out;

    gap_kernel<<<LBC / 2, 256>>>(in);
    fused_mul_kernel<<<LBC, 256>>>(in, Wm, out);
}